// round 15
// baseline (speedup 1.0000x reference)
#include <cuda_runtime.h>
#include <cuda_bf16.h>
#include <stdint.h>

#define BB 16
#define MM 1024
#define CC 128
#define BM (BB*MM)

// ---------------- device scratch ----------------
__device__ float g_n1[BM];
__device__ float g_n2[BM];
__device__ int g_idx1[BM];
__device__ unsigned long long g_idx2p[BM];
__device__ float g_part[3][2048];
__device__ __nv_bfloat16 g_h1[(size_t)BM * 128];   // bf16 rows, 256B each
__device__ __nv_bfloat16 g_h2[(size_t)BM * 128];
__device__ int g_done;

// ---------------- helpers ----------------
__device__ __forceinline__ uint32_t smem_u32(const void* p) {
    uint32_t a;
    asm("{ .reg .u64 t; cvta.to.shared.u64 t, %1; cvt.u32.u64 %0, t; }" : "=r"(a) : "l"(p));
    return a;
}
__device__ __forceinline__ unsigned int fenc(float f) {
    unsigned int u = __float_as_uint(f);
    return (u & 0x80000000u) ? ~u : (u | 0x80000000u);
}
__device__ __forceinline__ uint32_t pkbf(float lo, float hi) {
    return (uint32_t)__bfloat16_as_ushort(__float2bfloat16(lo)) |
           ((uint32_t)__bfloat16_as_ushort(__float2bfloat16(hi)) << 16);
}
__device__ __forceinline__ void cpa16(uint32_t dst, const void* src) {
    asm volatile("cp.async.cg.shared.global [%0], [%1], 16;" :: "r"(dst), "l"(src));
}
#define CP_COMMIT() asm volatile("cp.async.commit_group;" ::: "memory")
#define CP_WAIT(n)  asm volatile("cp.async.wait_group %0;" :: "n"(n) : "memory")

#define LDMX4(r0, r1, r2, r3, addr) \
    asm volatile("ldmatrix.sync.aligned.m8n8.x4.shared.b16 {%0,%1,%2,%3}, [%4];" \
        : "=r"(r0), "=r"(r1), "=r"(r2), "=r"(r3) : "r"(addr))

#define MMA16816(d, a0, a1, a2, a3, b0, b1) \
    asm volatile("mma.sync.aligned.m16n8k16.row.col.f32.bf16.bf16.f32 " \
        "{%0,%1,%2,%3}, {%4,%5,%6,%7}, {%8,%9}, {%0,%1,%2,%3};" \
        : "+f"((d)[0]), "+f"((d)[1]), "+f"((d)[2]), "+f"((d)[3]) \
        : "r"(a0), "r"(a1), "r"(a2), "r"(a3), "r"(b0), "r"(b1))

// ---------------- K1: transpose + packed bf16 + norms + idx2 init ----------------
// One-shot staging (32 LDGs in flight), single sync, then sync-free compute.
__global__ void __launch_bounds__(256) k_prep(const float* __restrict__ e1,
                                              const float* __restrict__ e2) {
    __shared__ float smf[2 * 128 * 33];   // [tensor][c][i] stride 33
    int b = blockIdx.y;
    int i0 = blockIdx.x * 32;
    int tid = threadIdx.x;                // 0..255 (1-D launch)

    if (tid < 32) g_idx2p[b * MM + i0 + tid] = ~0ULL;
    if (blockIdx.x == 0 && b == 0 && tid == 0) g_done = 0;

    // stage: 2 tensors x 128 c x 32 i, all loads issued back-to-back
    {
        const float* base1 = e1 + (size_t)b * CC * MM + i0;
        const float* base2 = e2 + (size_t)b * CC * MM + i0;
        int cl = tid >> 5;                // c within 8-c group, advanced by q
        int ii = tid & 31;
#pragma unroll
        for (int q = 0; q < 16; q++) {
            int c = cl + q * 8;
            smf[c * 33 + ii]              = base1[(size_t)c * MM + ii];
            smf[128 * 33 + c * 33 + ii]   = base2[(size_t)c * MM + ii];
        }
    }
    __syncthreads();

    int il_a = tid >> 4;        // 0..15
    int il_b = 16 + il_a;       // 16..31
    int cp = tid & 15;          // c-pair within 32-c chunk
    float n1a = 0.f, n1b = 0.f, n2a = 0.f, n2b = 0.f;

    uint32_t* h1 = (uint32_t*)g_h1;
    uint32_t* h2 = (uint32_t*)g_h2;

#pragma unroll
    for (int cc = 0; cc < 4; cc++) {
        int cbase = cc * 32 + 2 * cp;
        float a0 = smf[cbase * 33 + il_a],            a1 = smf[(cbase + 1) * 33 + il_a];
        float c0 = smf[4224 + cbase * 33 + il_a],     c1 = smf[4224 + (cbase + 1) * 33 + il_a];
        n1a += a0 * a0 + a1 * a1;
        n2a += c0 * c0 + c1 * c1;
        size_t basea = ((size_t)(b * MM + i0 + il_a)) * 64 + cc * 16 + cp;
        h1[basea] = pkbf(a0, a1);
        h2[basea] = pkbf(c0, c1);

        float b0 = smf[cbase * 33 + il_b],            b1 = smf[(cbase + 1) * 33 + il_b];
        float d0 = smf[4224 + cbase * 33 + il_b],     d1 = smf[4224 + (cbase + 1) * 33 + il_b];
        n1b += b0 * b0 + b1 * b1;
        n2b += d0 * d0 + d1 * d1;
        size_t baseb = ((size_t)(b * MM + i0 + il_b)) * 64 + cc * 16 + cp;
        h1[baseb] = pkbf(b0, b1);
        h2[baseb] = pkbf(d0, d1);
    }

#pragma unroll
    for (int off = 8; off >= 1; off >>= 1) {
        n1a += __shfl_xor_sync(0xFFFFFFFFu, n1a, off);
        n1b += __shfl_xor_sync(0xFFFFFFFFu, n1b, off);
        n2a += __shfl_xor_sync(0xFFFFFFFFu, n2a, off);
        n2b += __shfl_xor_sync(0xFFFFFFFFu, n2b, off);
    }
    if (cp == 0) {
        g_n1[b * MM + i0 + il_a] = n1a;
        g_n2[b * MM + i0 + il_a] = n2a;
        g_n1[b * MM + i0 + il_b] = n1b;
        g_n2[b * MM + i0 + il_b] = n2b;
    }
}

// ---------------- K2: pure-bf16 mma GEMM + dual argmin (16 warps) ----------------
#define ROWA 272
#define SM_A_SZ (128 * ROWA)                    // 34816
#define SM_SCOL (SM_A_SZ + 2 * 128 * ROWA)      // 104448
#define SM_SROW (SM_SCOL + 8192)                // 112640
#define SM_DOTS (SM_SROW + 1024)                // 113664

__global__ void __launch_bounds__(512, 1) k_dots() {
    extern __shared__ char smem[];
    uint32_t sb = smem_u32(smem);
    const uint32_t SA = sb;
    const uint32_t SB0 = sb + SM_A_SZ;
    unsigned long long* scol = (unsigned long long*)(smem + SM_SCOL);
    unsigned long long* srow = (unsigned long long*)(smem + SM_SROW);
    int tid = threadIdx.x, wid = tid >> 5, l = tid & 31;
    int b = blockIdx.y;
    int i0 = blockIdx.x * 128;
    const char* Ag = (const char*)(g_h1 + ((size_t)(b * MM + i0)) * 128);
    const char* Bg = (const char*)(g_h2 + ((size_t)b * MM) * 128);

#pragma unroll
    for (int q = 0; q < 4; q++) {
        int ch = tid + q * 512;
        int row = ch >> 4, c16 = ch & 15;
        cpa16(SA + row * ROWA + c16 * 16, Ag + row * 256 + c16 * 16);
    }
#pragma unroll
    for (int q = 0; q < 4; q++) {
        int ch = tid + q * 512;
        int row = ch >> 4, c16 = ch & 15;
        cpa16(SB0 + row * ROWA + c16 * 16, Bg + row * 256 + c16 * 16);
    }
    CP_COMMIT();

    for (int v = tid; v < 1024; v += 512) scol[v] = ~0ULL;
    if (tid < 128) srow[tid] = ~0ULL;

    int wy = wid >> 2, wx = wid & 3;
    int m0w = wy * 32, n0w = wx * 32;

    int rowA = (l & 7) + ((l >> 3) & 1) * 8;
    int koffA = (l >> 4) * 8;
    uint32_t aBase = SA + (uint32_t)(m0w + rowA) * ROWA + koffA * 2;
    int rowB = (l & 7) + ((l >> 4) & 1) * 8;
    int koffB = ((l >> 3) & 1) * 8;
    uint32_t bLane = (uint32_t)(n0w + rowB) * ROWA + koffB * 2;

    float n1r[2][2];
#pragma unroll
    for (int mf = 0; mf < 2; mf++)
#pragma unroll
        for (int h = 0; h < 2; h++)
            n1r[mf][h] = g_n1[b * MM + i0 + m0w + mf * 16 + (l >> 2) + h * 8];

    float rv[2][2];
    int ri[2][2];
#pragma unroll
    for (int mf = 0; mf < 2; mf++)
#pragma unroll
        for (int h = 0; h < 2; h++) { rv[mf][h] = 3.4e38f; ri[mf][h] = 0; }

#pragma unroll 1
    for (int jt = 0; jt < 8; jt++) {
        int j0 = jt * 128;
        __syncthreads();
        if (jt < 7) {
            const char* src = Bg + (size_t)(jt + 1) * 128 * 256;
            uint32_t dstb = SB0 + (uint32_t)((jt + 1) & 1) * 128 * ROWA;
#pragma unroll
            for (int q = 0; q < 4; q++) {
                int ch = tid + q * 512;
                int row = ch >> 4, c16 = ch & 15;
                cpa16(dstb + row * ROWA + c16 * 16, src + row * 256 + c16 * 16);
            }
            CP_COMMIT();
            CP_WAIT(1);
        } else {
            CP_WAIT(0);
        }
        __syncthreads();

        uint32_t bBase = SB0 + (uint32_t)(jt & 1) * 128 * ROWA + bLane;

        float acc[2][4][4];
#pragma unroll
        for (int mf = 0; mf < 2; mf++)
#pragma unroll
            for (int nf = 0; nf < 4; nf++)
#pragma unroll
                for (int r = 0; r < 4; r++) acc[mf][nf][r] = 0.f;

#pragma unroll
        for (int ks = 0; ks < 8; ks++) {
            uint32_t ao = (uint32_t)ks * 32u;
            uint32_t ahi[2][4], bhi[2][4];
#pragma unroll
            for (int mf = 0; mf < 2; mf++)
                LDMX4(ahi[mf][0], ahi[mf][1], ahi[mf][2], ahi[mf][3],
                      aBase + (uint32_t)mf * 16 * ROWA + ao);
#pragma unroll
            for (int np = 0; np < 2; np++)
                LDMX4(bhi[np][0], bhi[np][1], bhi[np][2], bhi[np][3],
                      bBase + (uint32_t)np * 16 * ROWA + ao);
#pragma unroll
            for (int mf = 0; mf < 2; mf++)
#pragma unroll
                for (int np = 0; np < 2; np++) {
                    MMA16816(acc[mf][np * 2],     ahi[mf][0], ahi[mf][1], ahi[mf][2], ahi[mf][3], bhi[np][0], bhi[np][1]);
                    MMA16816(acc[mf][np * 2 + 1], ahi[mf][0], ahi[mf][1], ahi[mf][2], ahi[mf][3], bhi[np][2], bhi[np][3]);
                }
        }

        // ---- epilogue ----
        float n2r[4][2];
#pragma unroll
        for (int nf = 0; nf < 4; nf++)
#pragma unroll
            for (int p = 0; p < 2; p++)
                n2r[nf][p] = g_n2[b * MM + j0 + n0w + nf * 8 + (l & 3) * 2 + p];

#pragma unroll
        for (int mf = 0; mf < 2; mf++)
#pragma unroll
            for (int h = 0; h < 2; h++) {
#pragma unroll
                for (int nf = 0; nf < 4; nf++)
#pragma unroll
                    for (int p = 0; p < 2; p++) {
                        float val = fmaf(-2.f, acc[mf][nf][h * 2 + p], n2r[nf][p]);
                        int j = j0 + n0w + nf * 8 + (l & 3) * 2 + p;
                        if (val < rv[mf][h]) { rv[mf][h] = val; ri[mf][h] = j; }
                    }
            }

#pragma unroll
        for (int nf = 0; nf < 4; nf++)
#pragma unroll
            for (int p = 0; p < 2; p++) {
                float cv = 3.4e38f;
                int ci = 0;
#pragma unroll
                for (int mf = 0; mf < 2; mf++)
#pragma unroll
                    for (int h = 0; h < 2; h++) {
                        float val = fmaf(-2.f, acc[mf][nf][h * 2 + p], n1r[mf][h]);
                        int i = i0 + m0w + mf * 16 + (l >> 2) + h * 8;
                        if (val < cv) { cv = val; ci = i; }
                    }
#pragma unroll
                for (int off = 4; off <= 16; off <<= 1) {
                    float ov = __shfl_xor_sync(0xFFFFFFFFu, cv, off);
                    int oi = __shfl_xor_sync(0xFFFFFFFFu, ci, off);
                    if (ov < cv || (ov == cv && oi < ci)) { cv = ov; ci = oi; }
                }
                if (l < 4)
                    atomicMin(&scol[j0 + n0w + nf * 8 + (l & 3) * 2 + p],
                              ((unsigned long long)fenc(cv) << 32) | (unsigned)ci);
            }
    }

    // flush row minima via shared atomicMin (4 warps share each row)
#pragma unroll
    for (int mf = 0; mf < 2; mf++)
#pragma unroll
        for (int h = 0; h < 2; h++) {
            float v = rv[mf][h];
            int idx = ri[mf][h];
#pragma unroll
            for (int off = 1; off <= 2; off <<= 1) {
                float ov = __shfl_xor_sync(0xFFFFFFFFu, v, off);
                int oi = __shfl_xor_sync(0xFFFFFFFFu, idx, off);
                if (ov < v || (ov == v && oi < idx)) { v = ov; idx = oi; }
            }
            if ((l & 3) == 0)
                atomicMin(&srow[m0w + mf * 16 + (l >> 2) + h * 8],
                          ((unsigned long long)fenc(v) << 32) | (unsigned)idx);
        }

    __syncthreads();
    if (tid < 128)
        g_idx1[b * MM + i0 + tid] = (int)(srow[tid] & 0xFFFFFFFFULL);
    for (int v = tid; v < 1024; v += 512)
        atomicMin(&g_idx2p[b * MM + v], scol[v]);
}

// ---------------- K3: both pairs per position; Gram on all 4 warps ----------------
__global__ void __launch_bounds__(128) k_stats(float* __restrict__ out) {
    __shared__ __align__(16) uint32_t Raw[64][66];          // 64 rows x 64 u32 (+2 pad)
    __shared__ __align__(16) __nv_bfloat16 Xb[4][16][136];  // [unit*2+tensor][b][c]
    __shared__ float sred[2][3][4];
    __shared__ float sGram[4];
    __shared__ int sidx[32];
    __shared__ int amLast;
    int i = blockIdx.x;
    int c = threadIdx.x;
    int wid = c >> 5, l = c & 31;

    if (c < 16)       sidx[c] = g_idx1[c * MM + i];
    else if (c < 32)  sidx[c] = (int)(g_idx2p[(c - 16) * MM + i] & 0xFFFFFFFFULL);
    __syncthreads();

    // stage 64 rows:
    //  r  0..15: x of unit0 = m1[b][i]
    //  r 16..31: y of unit0 = m2[b][idx1[b,i]]
    //  r 32..47: x of unit1 = m2[b][i]
    //  r 48..63: y of unit1 = m1[b][idx2[b,i]]
#pragma unroll
    for (int q = 0; q < 32; q++) {
        int t = c + q * 128;
        int r = t >> 6;
        int w = t & 63;
        int b = r & 15;
        const __nv_bfloat16* src;
        switch (r >> 4) {
            case 0:  src = g_h1 + ((size_t)b * MM + i) * 128; break;
            case 1:  src = g_h2 + ((size_t)b * MM + sidx[b]) * 128; break;
            case 2:  src = g_h2 + ((size_t)b * MM + i) * 128; break;
            default: src = g_h1 + ((size_t)b * MM + sidx[16 + b]) * 128; break;
        }
        Raw[r][w] = ((const uint32_t*)src)[w];
    }
    __syncthreads();

    float v0[2], v1[2], v2[2];
#pragma unroll
    for (int u = 0; u < 2; u++) {
        float x[16], y[16];
#pragma unroll
        for (int b = 0; b < 16; b++) {
            x[b] = __bfloat162float(((const __nv_bfloat16*)&Raw[u * 32 + b][0])[c]);
            y[b] = __bfloat162float(((const __nv_bfloat16*)&Raw[u * 32 + 16 + b][0])[c]);
        }

        float repr = 0.f;
#pragma unroll
        for (int b = 0; b < 16; b++) { float d = x[b] - y[b]; repr += d * d; }

        float mux = 0.f, muy = 0.f;
#pragma unroll
        for (int b = 0; b < 16; b++) { mux += x[b]; muy += y[b]; }
        mux *= (1.f / 16.f); muy *= (1.f / 16.f);

        float sx = 0.f, sy = 0.f;
#pragma unroll
        for (int b = 0; b < 16; b++) {
            x[b] -= mux; sx += x[b] * x[b];
            y[b] -= muy; sy += y[b] * y[b];
        }
        float stdp = fmaxf(0.f, 1.f - sqrtf(sx * (1.f / 15.f) + 1e-4f))
                   + fmaxf(0.f, 1.f - sqrtf(sy * (1.f / 15.f) + 1e-4f));
        float S2 = sx * sx + sy * sy;

#pragma unroll
        for (int b = 0; b < 16; b++) {
            Xb[u * 2][b][c]     = __float2bfloat16(x[b]);
            Xb[u * 2 + 1][b][c] = __float2bfloat16(y[b]);
        }
        v0[u] = repr; v1[u] = stdp; v2[u] = -S2;
    }
    __syncthreads();

    // warp-reduce the six scalars
#pragma unroll
    for (int u = 0; u < 2; u++) {
#pragma unroll
        for (int off = 16; off >= 1; off >>= 1) {
            v0[u] += __shfl_down_sync(0xFFFFFFFFu, v0[u], off);
            v1[u] += __shfl_down_sync(0xFFFFFFFFu, v1[u], off);
            v2[u] += __shfl_down_sync(0xFFFFFFFFu, v2[u], off);
        }
        if (l == 0) {
            sred[u][0][wid] = v0[u];
            sred[u][1][wid] = v1[u];
            sred[u][2][wid] = v2[u];
        }
    }

    // Gram: warp w handles Xb[w] (unit = w>>1, tensor = w&1)
    {
        int rowA = (l & 7) + ((l >> 3) & 1) * 8;
        int koffA = (l >> 4) * 8;
        int rowB = (l & 7) + ((l >> 4) & 1) * 8;
        int koffB = ((l >> 3) & 1) * 8;
        uint32_t tb = smem_u32(&Xb[wid][0][0]);
        uint32_t aB = tb + (uint32_t)rowA * 272 + koffA * 2;
        uint32_t bB = tb + (uint32_t)rowB * 272 + koffB * 2;
        float acc[8];
#pragma unroll
        for (int r = 0; r < 8; r++) acc[r] = 0.f;
#pragma unroll
        for (int ks = 0; ks < 8; ks++) {
            uint32_t a0, a1, a2, a3, b0, b1, b2, b3;
            LDMX4(a0, a1, a2, a3, aB + ks * 32);
            LDMX4(b0, b1, b2, b3, bB + ks * 32);
            MMA16816(acc,     a0, a1, a2, a3, b0, b1);
            MMA16816(acc + 4, a0, a1, a2, a3, b2, b3);
        }
        float gs = 0.f;
#pragma unroll
        for (int r = 0; r < 8; r++) gs = fmaf(acc[r], acc[r], gs);
#pragma unroll
        for (int off = 16; off >= 1; off >>= 1)
            gs += __shfl_down_sync(0xFFFFFFFFu, gs, off);
        if (l == 0) sGram[wid] = gs;
    }
    __syncthreads();

    if (c == 0) {
#pragma unroll
        for (int u = 0; u < 2; u++) {
            int blk = u * 1024 + i;
            g_part[0][blk] = sred[u][0][0] + sred[u][0][1] + sred[u][0][2] + sred[u][0][3];
            g_part[1][blk] = sred[u][1][0] + sred[u][1][1] + sred[u][1][2] + sred[u][1][3];
            g_part[2][blk] = sred[u][2][0] + sred[u][2][1] + sred[u][2][2] + sred[u][2][3]
                           + sGram[u * 2] + sGram[u * 2 + 1];
        }
        __threadfence();
        amLast = (atomicAdd(&g_done, 1) == 1023);
    }
    __syncthreads();

    if (amLast) {
        __shared__ float fred[3][4];
#pragma unroll 1
        for (int s = 0; s < 3; s++) {
            float v = 0.f;
            for (int k = c; k < 2048; k += 128) v += g_part[s][k];
#pragma unroll
            for (int off = 16; off >= 1; off >>= 1)
                v += __shfl_down_sync(0xFFFFFFFFu, v, off);
            if ((c & 31) == 0) fred[s][c >> 5] = v;
        }
        __syncthreads();
        if (c < 3) {
            float tot = fred[c][0] + fred[c][1] + fred[c][2] + fred[c][3];
            float scale;
            if (c == 0)      scale = 25.f / (2.f * 2097152.f);
            else if (c == 1) scale = 25.f / (4.f * 131072.f);
            else             scale = 1.f / (225.f * 524288.f);
            out[c] = tot * scale;
        }
    }
}

// ---------------- launch ----------------
extern "C" void kernel_launch(void* const* d_in, const int* in_sizes, int n_in,
                              void* d_out, int out_size) {
    const float* e1 = (const float*)d_in[0];
    const float* e2 = (const float*)d_in[1];
    float* out = (float*)d_out;
    (void)in_sizes; (void)n_in; (void)out_size;

    cudaFuncSetAttribute(k_dots, cudaFuncAttributeMaxDynamicSharedMemorySize, SM_DOTS);

    k_prep<<<dim3(32, 16), 256>>>(e1, e2);
    k_dots<<<dim3(8, 16), 512, SM_DOTS>>>();
    k_stats<<<MM, 128>>>(out);
}

// round 16
// speedup vs baseline: 1.0768x; 1.0768x over previous
#include <cuda_runtime.h>
#include <cuda_bf16.h>
#include <stdint.h>

#define BB 16
#define MM 1024
#define CC 128
#define BM (BB*MM)

// ---------------- device scratch ----------------
__device__ float g_n1[BM];
__device__ float g_n2[BM];
__device__ int g_idx1[BM];
__device__ unsigned long long g_idx2p[BM];
__device__ float g_part[3][2048];
__device__ __nv_bfloat16 g_h1[(size_t)BM * 128];   // bf16 rows, 256B each
__device__ __nv_bfloat16 g_h2[(size_t)BM * 128];
__device__ int g_done;

// ---------------- helpers ----------------
__device__ __forceinline__ uint32_t smem_u32(const void* p) {
    uint32_t a;
    asm("{ .reg .u64 t; cvta.to.shared.u64 t, %1; cvt.u32.u64 %0, t; }" : "=r"(a) : "l"(p));
    return a;
}
__device__ __forceinline__ unsigned int fenc(float f) {
    unsigned int u = __float_as_uint(f);
    return (u & 0x80000000u) ? ~u : (u | 0x80000000u);
}
__device__ __forceinline__ uint32_t pkbf(float lo, float hi) {
    return (uint32_t)__bfloat16_as_ushort(__float2bfloat16(lo)) |
           ((uint32_t)__bfloat16_as_ushort(__float2bfloat16(hi)) << 16);
}
__device__ __forceinline__ void cpa16(uint32_t dst, const void* src) {
    asm volatile("cp.async.cg.shared.global [%0], [%1], 16;" :: "r"(dst), "l"(src));
}
#define CP_COMMIT() asm volatile("cp.async.commit_group;" ::: "memory")
#define CP_WAIT(n)  asm volatile("cp.async.wait_group %0;" :: "n"(n) : "memory")

#define LDMX4(r0, r1, r2, r3, addr) \
    asm volatile("ldmatrix.sync.aligned.m8n8.x4.shared.b16 {%0,%1,%2,%3}, [%4];" \
        : "=r"(r0), "=r"(r1), "=r"(r2), "=r"(r3) : "r"(addr))

#define MMA16816(d, a0, a1, a2, a3, b0, b1) \
    asm volatile("mma.sync.aligned.m16n8k16.row.col.f32.bf16.bf16.f32 " \
        "{%0,%1,%2,%3}, {%4,%5,%6,%7}, {%8,%9}, {%0,%1,%2,%3};" \
        : "+f"((d)[0]), "+f"((d)[1]), "+f"((d)[2]), "+f"((d)[3]) \
        : "r"(a0), "r"(a1), "r"(a2), "r"(a3), "r"(b0), "r"(b1))

// ---------------- K1: transpose + packed bf16 + norms + idx2 init ----------------
// 1024 blocks (16-row i-tiles) for 2x thread-level parallelism (L2-latency-bound).
__global__ void __launch_bounds__(256) k_prep(const float* __restrict__ e1,
                                              const float* __restrict__ e2) {
    __shared__ float smf[2 * 128 * 17];   // [tensor][c][i] stride 17
    int b = blockIdx.y;
    int i0 = blockIdx.x * 16;
    int tid = threadIdx.x;                // 0..255

    if (tid < 16) g_idx2p[b * MM + i0 + tid] = ~0ULL;
    if (blockIdx.x == 0 && b == 0 && tid == 0) g_done = 0;

    // stage: 2 tensors x 128 c x 16 i
    {
        const float* base1 = e1 + (size_t)b * CC * MM + i0;
        const float* base2 = e2 + (size_t)b * CC * MM + i0;
        int ii = tid & 15;
        int c0 = tid >> 4;                // 0..15
#pragma unroll
        for (int q = 0; q < 8; q++) {
            int c = c0 + q * 16;
            smf[c * 17 + ii]        = base1[(size_t)c * MM + ii];
            smf[2176 + c * 17 + ii] = base2[(size_t)c * MM + ii];
        }
    }
    __syncthreads();

    int il = tid >> 4;          // 0..15 (row within tile)
    int cp = tid & 15;          // c-pair within 32-c chunk
    float n1 = 0.f, n2 = 0.f;

    uint32_t* h1 = (uint32_t*)g_h1;
    uint32_t* h2 = (uint32_t*)g_h2;

#pragma unroll
    for (int cc = 0; cc < 4; cc++) {
        int cb = cc * 32 + 2 * cp;
        float a0 = smf[cb * 17 + il],        a1 = smf[(cb + 1) * 17 + il];
        float c0v = smf[2176 + cb * 17 + il], c1v = smf[2176 + (cb + 1) * 17 + il];
        n1 += a0 * a0 + a1 * a1;
        n2 += c0v * c0v + c1v * c1v;
        size_t base = ((size_t)(b * MM + i0 + il)) * 64 + cc * 16 + cp;
        h1[base] = pkbf(a0, a1);
        h2[base] = pkbf(c0v, c1v);
    }

#pragma unroll
    for (int off = 8; off >= 1; off >>= 1) {
        n1 += __shfl_xor_sync(0xFFFFFFFFu, n1, off);
        n2 += __shfl_xor_sync(0xFFFFFFFFu, n2, off);
    }
    if (cp == 0) {
        g_n1[b * MM + i0 + il] = n1;
        g_n2[b * MM + i0 + il] = n2;
    }
}

// ---------------- K2: pure-bf16 mma GEMM + dual argmin (16 warps) ----------------
#define ROWA 272
#define SM_A_SZ (128 * ROWA)                    // 34816
#define SM_SCOL (SM_A_SZ + 2 * 128 * ROWA)      // 104448
#define SM_SROW (SM_SCOL + 8192)                // 112640
#define SM_DOTS (SM_SROW + 1024)                // 113664

__global__ void __launch_bounds__(512, 1) k_dots() {
    extern __shared__ char smem[];
    uint32_t sb = smem_u32(smem);
    const uint32_t SA = sb;
    const uint32_t SB0 = sb + SM_A_SZ;
    unsigned long long* scol = (unsigned long long*)(smem + SM_SCOL);
    unsigned long long* srow = (unsigned long long*)(smem + SM_SROW);
    int tid = threadIdx.x, wid = tid >> 5, l = tid & 31;
    int b = blockIdx.y;
    int i0 = blockIdx.x * 128;
    const char* Ag = (const char*)(g_h1 + ((size_t)(b * MM + i0)) * 128);
    const char* Bg = (const char*)(g_h2 + ((size_t)b * MM) * 128);

#pragma unroll
    for (int q = 0; q < 4; q++) {
        int ch = tid + q * 512;
        int row = ch >> 4, c16 = ch & 15;
        cpa16(SA + row * ROWA + c16 * 16, Ag + row * 256 + c16 * 16);
    }
#pragma unroll
    for (int q = 0; q < 4; q++) {
        int ch = tid + q * 512;
        int row = ch >> 4, c16 = ch & 15;
        cpa16(SB0 + row * ROWA + c16 * 16, Bg + row * 256 + c16 * 16);
    }
    CP_COMMIT();

    for (int v = tid; v < 1024; v += 512) scol[v] = ~0ULL;
    if (tid < 128) srow[tid] = ~0ULL;

    int wy = wid >> 2, wx = wid & 3;
    int m0w = wy * 32, n0w = wx * 32;

    int rowA = (l & 7) + ((l >> 3) & 1) * 8;
    int koffA = (l >> 4) * 8;
    uint32_t aBase = SA + (uint32_t)(m0w + rowA) * ROWA + koffA * 2;
    int rowB = (l & 7) + ((l >> 4) & 1) * 8;
    int koffB = ((l >> 3) & 1) * 8;
    uint32_t bLane = (uint32_t)(n0w + rowB) * ROWA + koffB * 2;

    float n1r[2][2];
#pragma unroll
    for (int mf = 0; mf < 2; mf++)
#pragma unroll
        for (int h = 0; h < 2; h++)
            n1r[mf][h] = g_n1[b * MM + i0 + m0w + mf * 16 + (l >> 2) + h * 8];

    float rv[2][2];
    int ri[2][2];
#pragma unroll
    for (int mf = 0; mf < 2; mf++)
#pragma unroll
        for (int h = 0; h < 2; h++) { rv[mf][h] = 3.4e38f; ri[mf][h] = 0; }

#pragma unroll 1
    for (int jt = 0; jt < 8; jt++) {
        int j0 = jt * 128;
        __syncthreads();
        if (jt < 7) {
            const char* src = Bg + (size_t)(jt + 1) * 128 * 256;
            uint32_t dstb = SB0 + (uint32_t)((jt + 1) & 1) * 128 * ROWA;
#pragma unroll
            for (int q = 0; q < 4; q++) {
                int ch = tid + q * 512;
                int row = ch >> 4, c16 = ch & 15;
                cpa16(dstb + row * ROWA + c16 * 16, src + row * 256 + c16 * 16);
            }
            CP_COMMIT();
            CP_WAIT(1);
        } else {
            CP_WAIT(0);
        }
        __syncthreads();

        uint32_t bBase = SB0 + (uint32_t)(jt & 1) * 128 * ROWA + bLane;

        float acc[2][4][4];
#pragma unroll
        for (int mf = 0; mf < 2; mf++)
#pragma unroll
            for (int nf = 0; nf < 4; nf++)
#pragma unroll
                for (int r = 0; r < 4; r++) acc[mf][nf][r] = 0.f;

#pragma unroll
        for (int ks = 0; ks < 8; ks++) {
            uint32_t ao = (uint32_t)ks * 32u;
            uint32_t ahi[2][4], bhi[2][4];
#pragma unroll
            for (int mf = 0; mf < 2; mf++)
                LDMX4(ahi[mf][0], ahi[mf][1], ahi[mf][2], ahi[mf][3],
                      aBase + (uint32_t)mf * 16 * ROWA + ao);
#pragma unroll
            for (int np = 0; np < 2; np++)
                LDMX4(bhi[np][0], bhi[np][1], bhi[np][2], bhi[np][3],
                      bBase + (uint32_t)np * 16 * ROWA + ao);
#pragma unroll
            for (int mf = 0; mf < 2; mf++)
#pragma unroll
                for (int np = 0; np < 2; np++) {
                    MMA16816(acc[mf][np * 2],     ahi[mf][0], ahi[mf][1], ahi[mf][2], ahi[mf][3], bhi[np][0], bhi[np][1]);
                    MMA16816(acc[mf][np * 2 + 1], ahi[mf][0], ahi[mf][1], ahi[mf][2], ahi[mf][3], bhi[np][2], bhi[np][3]);
                }
        }

        // ---- epilogue ----
        float n2r[4][2];
#pragma unroll
        for (int nf = 0; nf < 4; nf++)
#pragma unroll
            for (int p = 0; p < 2; p++)
                n2r[nf][p] = g_n2[b * MM + j0 + n0w + nf * 8 + (l & 3) * 2 + p];

#pragma unroll
        for (int mf = 0; mf < 2; mf++)
#pragma unroll
            for (int h = 0; h < 2; h++) {
#pragma unroll
                for (int nf = 0; nf < 4; nf++)
#pragma unroll
                    for (int p = 0; p < 2; p++) {
                        float val = fmaf(-2.f, acc[mf][nf][h * 2 + p], n2r[nf][p]);
                        int j = j0 + n0w + nf * 8 + (l & 3) * 2 + p;
                        if (val < rv[mf][h]) { rv[mf][h] = val; ri[mf][h] = j; }
                    }
            }

#pragma unroll
        for (int nf = 0; nf < 4; nf++)
#pragma unroll
            for (int p = 0; p < 2; p++) {
                float cv = 3.4e38f;
                int ci = 0;
#pragma unroll
                for (int mf = 0; mf < 2; mf++)
#pragma unroll
                    for (int h = 0; h < 2; h++) {
                        float val = fmaf(-2.f, acc[mf][nf][h * 2 + p], n1r[mf][h]);
                        int i = i0 + m0w + mf * 16 + (l >> 2) + h * 8;
                        if (val < cv) { cv = val; ci = i; }
                    }
#pragma unroll
                for (int off = 4; off <= 16; off <<= 1) {
                    float ov = __shfl_xor_sync(0xFFFFFFFFu, cv, off);
                    int oi = __shfl_xor_sync(0xFFFFFFFFu, ci, off);
                    if (ov < cv || (ov == cv && oi < ci)) { cv = ov; ci = oi; }
                }
                if (l < 4)
                    atomicMin(&scol[j0 + n0w + nf * 8 + (l & 3) * 2 + p],
                              ((unsigned long long)fenc(cv) << 32) | (unsigned)ci);
            }
    }

    // flush row minima via shared atomicMin (4 warps share each row)
#pragma unroll
    for (int mf = 0; mf < 2; mf++)
#pragma unroll
        for (int h = 0; h < 2; h++) {
            float v = rv[mf][h];
            int idx = ri[mf][h];
#pragma unroll
            for (int off = 1; off <= 2; off <<= 1) {
                float ov = __shfl_xor_sync(0xFFFFFFFFu, v, off);
                int oi = __shfl_xor_sync(0xFFFFFFFFu, idx, off);
                if (ov < v || (ov == v && oi < idx)) { v = ov; idx = oi; }
            }
            if ((l & 3) == 0)
                atomicMin(&srow[m0w + mf * 16 + (l >> 2) + h * 8],
                          ((unsigned long long)fenc(v) << 32) | (unsigned)idx);
        }

    __syncthreads();
    if (tid < 128)
        g_idx1[b * MM + i0 + tid] = (int)(srow[tid] & 0xFFFFFFFFULL);
    for (int v = tid; v < 1024; v += 512)
        atomicMin(&g_idx2p[b * MM + v], scol[v]);
}

// ---------------- K3: staged gather + vicreg stats + fused final ----------------
__global__ void __launch_bounds__(128) k_stats(float* __restrict__ out) {
    __shared__ __align__(16) uint32_t Raw[2][16][66];
    __shared__ __align__(16) __nv_bfloat16 Xb[2][16][136];
    __shared__ float sred[12];
    __shared__ int sidx[16];
    __shared__ int amLast;
    int i = blockIdx.x;
    int p = blockIdx.y;
    int c = threadIdx.x;
    const __nv_bfloat16* tx_ = p ? g_h2 : g_h1;
    const __nv_bfloat16* ty_ = p ? g_h1 : g_h2;

    if (c < 16)
        sidx[c] = p ? (int)(g_idx2p[c * MM + i] & 0xFFFFFFFFULL) : g_idx1[c * MM + i];
    __syncthreads();

#pragma unroll
    for (int q = 0; q < 16; q++) {
        int t = c + q * 128;
        int half = t >> 10;
        int b = (t >> 6) & 15;
        int w = t & 63;
        const __nv_bfloat16* src = half ? (ty_ + ((size_t)b * MM + sidx[b]) * 128)
                                        : (tx_ + ((size_t)b * MM + i) * 128);
        Raw[half][b][w] = ((const uint32_t*)src)[w];
    }
    __syncthreads();

    float x[16], y[16];
#pragma unroll
    for (int b = 0; b < 16; b++) {
        x[b] = __bfloat162float(((const __nv_bfloat16*)&Raw[0][b][0])[c]);
        y[b] = __bfloat162float(((const __nv_bfloat16*)&Raw[1][b][0])[c]);
    }

    float repr = 0.f;
#pragma unroll
    for (int b = 0; b < 16; b++) { float d = x[b] - y[b]; repr += d * d; }

    float mux = 0.f, muy = 0.f;
#pragma unroll
    for (int b = 0; b < 16; b++) { mux += x[b]; muy += y[b]; }
    mux *= (1.f / 16.f); muy *= (1.f / 16.f);

    float sx = 0.f, sy = 0.f;
#pragma unroll
    for (int b = 0; b < 16; b++) {
        x[b] -= mux; sx += x[b] * x[b];
        y[b] -= muy; sy += y[b] * y[b];
    }
    float stdp = fmaxf(0.f, 1.f - sqrtf(sx * (1.f / 15.f) + 1e-4f))
               + fmaxf(0.f, 1.f - sqrtf(sy * (1.f / 15.f) + 1e-4f));
    float S2 = sx * sx + sy * sy;

#pragma unroll
    for (int b = 0; b < 16; b++) {
        Xb[0][b][c] = __float2bfloat16(x[b]);
        Xb[1][b][c] = __float2bfloat16(y[b]);
    }
    __syncthreads();

    float covpart = -S2;
    int wid = c >> 5, l = c & 31;
    if (wid < 2) {
        int t = wid;
        int rowA = (l & 7) + ((l >> 3) & 1) * 8;
        int koffA = (l >> 4) * 8;
        int rowB = (l & 7) + ((l >> 4) & 1) * 8;
        int koffB = ((l >> 3) & 1) * 8;
        uint32_t tb = smem_u32(&Xb[0][0][0]) + (uint32_t)t * 16 * 272;
        uint32_t aB = tb + (uint32_t)rowA * 272 + koffA * 2;
        uint32_t bB = tb + (uint32_t)rowB * 272 + koffB * 2;
        float acc[8];
#pragma unroll
        for (int r = 0; r < 8; r++) acc[r] = 0.f;
#pragma unroll
        for (int ks = 0; ks < 8; ks++) {
            uint32_t a0, a1, a2, a3, b0, b1, b2, b3;
            LDMX4(a0, a1, a2, a3, aB + ks * 32);
            LDMX4(b0, b1, b2, b3, bB + ks * 32);
            MMA16816(acc,     a0, a1, a2, a3, b0, b1);
            MMA16816(acc + 4, a0, a1, a2, a3, b2, b3);
        }
#pragma unroll
        for (int r = 0; r < 8; r++)
            covpart = fmaf(acc[r], acc[r], covpart);
    }

    float v0 = repr, v1 = stdp, v2 = covpart;
#pragma unroll
    for (int off = 16; off >= 1; off >>= 1) {
        v0 += __shfl_down_sync(0xFFFFFFFFu, v0, off);
        v1 += __shfl_down_sync(0xFFFFFFFFu, v1, off);
        v2 += __shfl_down_sync(0xFFFFFFFFu, v2, off);
    }
    if ((c & 31) == 0) { sred[wid] = v0; sred[4 + wid] = v1; sred[8 + wid] = v2; }
    __syncthreads();
    if (c == 0) {
        int blk = p * 1024 + i;
        g_part[0][blk] = sred[0] + sred[1] + sred[2] + sred[3];
        g_part[1][blk] = sred[4] + sred[5] + sred[6] + sred[7];
        g_part[2][blk] = sred[8] + sred[9] + sred[10] + sred[11];
        __threadfence();
        amLast = (atomicAdd(&g_done, 1) == 2047);
    }
    __syncthreads();

    if (amLast) {
        __shared__ float fred[3][4];
#pragma unroll 1
        for (int s = 0; s < 3; s++) {
            float v = 0.f;
            for (int k = c; k < 2048; k += 128) v += g_part[s][k];
#pragma unroll
            for (int off = 16; off >= 1; off >>= 1)
                v += __shfl_down_sync(0xFFFFFFFFu, v, off);
            if ((c & 31) == 0) fred[s][c >> 5] = v;
        }
        __syncthreads();
        if (c < 3) {
            float tot = fred[c][0] + fred[c][1] + fred[c][2] + fred[c][3];
            float scale;
            if (c == 0)      scale = 25.f / (2.f * 2097152.f);
            else if (c == 1) scale = 25.f / (4.f * 131072.f);
            else             scale = 1.f / (225.f * 524288.f);
            out[c] = tot * scale;
        }
    }
}

// ---------------- launch ----------------
extern "C" void kernel_launch(void* const* d_in, const int* in_sizes, int n_in,
                              void* d_out, int out_size) {
    const float* e1 = (const float*)d_in[0];
    const float* e2 = (const float*)d_in[1];
    float* out = (float*)d_out;
    (void)in_sizes; (void)n_in; (void)out_size;

    cudaFuncSetAttribute(k_dots, cudaFuncAttributeMaxDynamicSharedMemorySize, SM_DOTS);

    k_prep<<<dim3(64, 16), 256>>>(e1, e2);
    k_dots<<<dim3(8, 16), 512, SM_DOTS>>>();
    k_stats<<<dim3(MM, 2), 128>>>(out);
}

// round 17
// speedup vs baseline: 1.1035x; 1.0248x over previous
#include <cuda_runtime.h>
#include <cuda_bf16.h>
#include <stdint.h>

#define BB 16
#define MM 1024
#define CC 128
#define BM (BB*MM)

// ---------------- device scratch ----------------
__device__ float g_n1[BM];
__device__ float g_n2[BM];
__device__ int g_idx1[BM];
__device__ unsigned long long g_idx2p[BM];
__device__ float g_part[3][2048];
__device__ __nv_bfloat16 g_h1[(size_t)BM * 128];   // bf16 rows, 256B each
__device__ __nv_bfloat16 g_h2[(size_t)BM * 128];
__device__ int g_done;

// ---------------- helpers ----------------
__device__ __forceinline__ uint32_t smem_u32(const void* p) {
    uint32_t a;
    asm("{ .reg .u64 t; cvta.to.shared.u64 t, %1; cvt.u32.u64 %0, t; }" : "=r"(a) : "l"(p));
    return a;
}
__device__ __forceinline__ unsigned int fenc(float f) {
    unsigned int u = __float_as_uint(f);
    return (u & 0x80000000u) ? ~u : (u | 0x80000000u);
}
__device__ __forceinline__ uint32_t pkbf(float lo, float hi) {
    return (uint32_t)__bfloat16_as_ushort(__float2bfloat16(lo)) |
           ((uint32_t)__bfloat16_as_ushort(__float2bfloat16(hi)) << 16);
}
__device__ __forceinline__ void cpa16(uint32_t dst, const void* src) {
    asm volatile("cp.async.cg.shared.global [%0], [%1], 16;" :: "r"(dst), "l"(src));
}
#define CP_COMMIT() asm volatile("cp.async.commit_group;" ::: "memory")
#define CP_WAIT(n)  asm volatile("cp.async.wait_group %0;" :: "n"(n) : "memory")

#define LDMX4(r0, r1, r2, r3, addr) \
    asm volatile("ldmatrix.sync.aligned.m8n8.x4.shared.b16 {%0,%1,%2,%3}, [%4];" \
        : "=r"(r0), "=r"(r1), "=r"(r2), "=r"(r3) : "r"(addr))

#define MMA16816(d, a0, a1, a2, a3, b0, b1) \
    asm volatile("mma.sync.aligned.m16n8k16.row.col.f32.bf16.bf16.f32 " \
        "{%0,%1,%2,%3}, {%4,%5,%6,%7}, {%8,%9}, {%0,%1,%2,%3};" \
        : "+f"((d)[0]), "+f"((d)[1]), "+f"((d)[2]), "+f"((d)[3]) \
        : "r"(a0), "r"(a1), "r"(a2), "r"(a3), "r"(b0), "r"(b1))

// ---------------- K1: transpose + packed bf16 + norms + idx2 init ----------------
// 1024 blocks (16-row i-tiles); float4 staging loads (LSU-issue-bound kernel).
__global__ void __launch_bounds__(256) k_prep(const float* __restrict__ e1,
                                              const float* __restrict__ e2) {
    __shared__ float smf[2 * 128 * 17];   // [tensor][c][i] stride 17
    int b = blockIdx.y;
    int i0 = blockIdx.x * 16;
    int tid = threadIdx.x;                // 0..255

    if (tid < 16) g_idx2p[b * MM + i0 + tid] = ~0ULL;
    if (blockIdx.x == 0 && b == 0 && tid == 0) g_done = 0;

    // stage: 1024 float4 chunks (2 tensors x 128 c x 4 i4), 4 per thread
    {
        const float* base1 = e1 + (size_t)b * CC * MM + i0;
        const float* base2 = e2 + (size_t)b * CC * MM + i0;
#pragma unroll
        for (int q = 0; q < 4; q++) {
            int id = tid + q * 256;
            int i4 = id & 3;
            int c = (id >> 2) & 127;
            int ten = id >> 9;
            const float* s = ten ? base2 : base1;
            float4 v = *(const float4*)(s + (size_t)c * MM + i4 * 4);
            float* d = smf + ten * 2176 + c * 17 + i4 * 4;
            d[0] = v.x; d[1] = v.y; d[2] = v.z; d[3] = v.w;
        }
    }
    __syncthreads();

    int il = tid >> 4;          // 0..15 (row within tile)
    int cp = tid & 15;          // c-pair within 32-c chunk
    float n1 = 0.f, n2 = 0.f;

    uint32_t* h1 = (uint32_t*)g_h1;
    uint32_t* h2 = (uint32_t*)g_h2;

#pragma unroll
    for (int cc = 0; cc < 4; cc++) {
        int cb = cc * 32 + 2 * cp;
        float a0 = smf[cb * 17 + il],         a1 = smf[(cb + 1) * 17 + il];
        float c0v = smf[2176 + cb * 17 + il], c1v = smf[2176 + (cb + 1) * 17 + il];
        n1 += a0 * a0 + a1 * a1;
        n2 += c0v * c0v + c1v * c1v;
        size_t base = ((size_t)(b * MM + i0 + il)) * 64 + cc * 16 + cp;
        h1[base] = pkbf(a0, a1);
        h2[base] = pkbf(c0v, c1v);
    }

#pragma unroll
    for (int off = 8; off >= 1; off >>= 1) {
        n1 += __shfl_xor_sync(0xFFFFFFFFu, n1, off);
        n2 += __shfl_xor_sync(0xFFFFFFFFu, n2, off);
    }
    if (cp == 0) {
        g_n1[b * MM + i0 + il] = n1;
        g_n2[b * MM + i0 + il] = n2;
    }
}

// ---------------- K2: pure-bf16 mma GEMM + dual argmin (16 warps) ----------------
#define ROWA 272
#define SM_A_SZ (128 * ROWA)                    // 34816
#define SM_SCOL (SM_A_SZ + 2 * 128 * ROWA)      // 104448
#define SM_SROW (SM_SCOL + 8192)                // 112640
#define SM_DOTS (SM_SROW + 1024)                // 113664

__global__ void __launch_bounds__(512, 1) k_dots() {
    extern __shared__ char smem[];
    uint32_t sb = smem_u32(smem);
    const uint32_t SA = sb;
    const uint32_t SB0 = sb + SM_A_SZ;
    unsigned long long* scol = (unsigned long long*)(smem + SM_SCOL);
    unsigned long long* srow = (unsigned long long*)(smem + SM_SROW);
    int tid = threadIdx.x, wid = tid >> 5, l = tid & 31;
    int b = blockIdx.y;
    int i0 = blockIdx.x * 128;
    const char* Ag = (const char*)(g_h1 + ((size_t)(b * MM + i0)) * 128);
    const char* Bg = (const char*)(g_h2 + ((size_t)b * MM) * 128);

#pragma unroll
    for (int q = 0; q < 4; q++) {
        int ch = tid + q * 512;
        int row = ch >> 4, c16 = ch & 15;
        cpa16(SA + row * ROWA + c16 * 16, Ag + row * 256 + c16 * 16);
    }
#pragma unroll
    for (int q = 0; q < 4; q++) {
        int ch = tid + q * 512;
        int row = ch >> 4, c16 = ch & 15;
        cpa16(SB0 + row * ROWA + c16 * 16, Bg + row * 256 + c16 * 16);
    }
    CP_COMMIT();

    for (int v = tid; v < 1024; v += 512) scol[v] = ~0ULL;
    if (tid < 128) srow[tid] = ~0ULL;

    int wy = wid >> 2, wx = wid & 3;
    int m0w = wy * 32, n0w = wx * 32;

    int rowA = (l & 7) + ((l >> 3) & 1) * 8;
    int koffA = (l >> 4) * 8;
    uint32_t aBase = SA + (uint32_t)(m0w + rowA) * ROWA + koffA * 2;
    int rowB = (l & 7) + ((l >> 4) & 1) * 8;
    int koffB = ((l >> 3) & 1) * 8;
    uint32_t bLane = (uint32_t)(n0w + rowB) * ROWA + koffB * 2;

    float n1r[2][2];
#pragma unroll
    for (int mf = 0; mf < 2; mf++)
#pragma unroll
        for (int h = 0; h < 2; h++)
            n1r[mf][h] = g_n1[b * MM + i0 + m0w + mf * 16 + (l >> 2) + h * 8];

    float rv[2][2];
    int ri[2][2];
#pragma unroll
    for (int mf = 0; mf < 2; mf++)
#pragma unroll
        for (int h = 0; h < 2; h++) { rv[mf][h] = 3.4e38f; ri[mf][h] = 0; }

#pragma unroll 1
    for (int jt = 0; jt < 8; jt++) {
        int j0 = jt * 128;
        __syncthreads();
        if (jt < 7) {
            const char* src = Bg + (size_t)(jt + 1) * 128 * 256;
            uint32_t dstb = SB0 + (uint32_t)((jt + 1) & 1) * 128 * ROWA;
#pragma unroll
            for (int q = 0; q < 4; q++) {
                int ch = tid + q * 512;
                int row = ch >> 4, c16 = ch & 15;
                cpa16(dstb + row * ROWA + c16 * 16, src + row * 256 + c16 * 16);
            }
            CP_COMMIT();
            CP_WAIT(1);
        } else {
            CP_WAIT(0);
        }
        __syncthreads();

        uint32_t bBase = SB0 + (uint32_t)(jt & 1) * 128 * ROWA + bLane;

        float acc[2][4][4];
#pragma unroll
        for (int mf = 0; mf < 2; mf++)
#pragma unroll
            for (int nf = 0; nf < 4; nf++)
#pragma unroll
                for (int r = 0; r < 4; r++) acc[mf][nf][r] = 0.f;

#pragma unroll
        for (int ks = 0; ks < 8; ks++) {
            uint32_t ao = (uint32_t)ks * 32u;
            uint32_t ahi[2][4], bhi[2][4];
#pragma unroll
            for (int mf = 0; mf < 2; mf++)
                LDMX4(ahi[mf][0], ahi[mf][1], ahi[mf][2], ahi[mf][3],
                      aBase + (uint32_t)mf * 16 * ROWA + ao);
#pragma unroll
            for (int np = 0; np < 2; np++)
                LDMX4(bhi[np][0], bhi[np][1], bhi[np][2], bhi[np][3],
                      bBase + (uint32_t)np * 16 * ROWA + ao);
#pragma unroll
            for (int mf = 0; mf < 2; mf++)
#pragma unroll
                for (int np = 0; np < 2; np++) {
                    MMA16816(acc[mf][np * 2],     ahi[mf][0], ahi[mf][1], ahi[mf][2], ahi[mf][3], bhi[np][0], bhi[np][1]);
                    MMA16816(acc[mf][np * 2 + 1], ahi[mf][0], ahi[mf][1], ahi[mf][2], ahi[mf][3], bhi[np][2], bhi[np][3]);
                }
        }

        // ---- epilogue ----
        float n2r[4][2];
#pragma unroll
        for (int nf = 0; nf < 4; nf++)
#pragma unroll
            for (int p = 0; p < 2; p++)
                n2r[nf][p] = g_n2[b * MM + j0 + n0w + nf * 8 + (l & 3) * 2 + p];

#pragma unroll
        for (int mf = 0; mf < 2; mf++)
#pragma unroll
            for (int h = 0; h < 2; h++) {
#pragma unroll
                for (int nf = 0; nf < 4; nf++)
#pragma unroll
                    for (int p = 0; p < 2; p++) {
                        float val = fmaf(-2.f, acc[mf][nf][h * 2 + p], n2r[nf][p]);
                        int j = j0 + n0w + nf * 8 + (l & 3) * 2 + p;
                        if (val < rv[mf][h]) { rv[mf][h] = val; ri[mf][h] = j; }
                    }
            }

#pragma unroll
        for (int nf = 0; nf < 4; nf++)
#pragma unroll
            for (int p = 0; p < 2; p++) {
                float cv = 3.4e38f;
                int ci = 0;
#pragma unroll
                for (int mf = 0; mf < 2; mf++)
#pragma unroll
                    for (int h = 0; h < 2; h++) {
                        float val = fmaf(-2.f, acc[mf][nf][h * 2 + p], n1r[mf][h]);
                        int i = i0 + m0w + mf * 16 + (l >> 2) + h * 8;
                        if (val < cv) { cv = val; ci = i; }
                    }
#pragma unroll
                for (int off = 4; off <= 16; off <<= 1) {
                    float ov = __shfl_xor_sync(0xFFFFFFFFu, cv, off);
                    int oi = __shfl_xor_sync(0xFFFFFFFFu, ci, off);
                    if (ov < cv || (ov == cv && oi < ci)) { cv = ov; ci = oi; }
                }
                if (l < 4)
                    atomicMin(&scol[j0 + n0w + nf * 8 + (l & 3) * 2 + p],
                              ((unsigned long long)fenc(cv) << 32) | (unsigned)ci);
            }
    }

    // flush row minima via shared atomicMin (4 warps share each row)
#pragma unroll
    for (int mf = 0; mf < 2; mf++)
#pragma unroll
        for (int h = 0; h < 2; h++) {
            float v = rv[mf][h];
            int idx = ri[mf][h];
#pragma unroll
            for (int off = 1; off <= 2; off <<= 1) {
                float ov = __shfl_xor_sync(0xFFFFFFFFu, v, off);
                int oi = __shfl_xor_sync(0xFFFFFFFFu, idx, off);
                if (ov < v || (ov == v && oi < idx)) { v = ov; idx = oi; }
            }
            if ((l & 3) == 0)
                atomicMin(&srow[m0w + mf * 16 + (l >> 2) + h * 8],
                          ((unsigned long long)fenc(v) << 32) | (unsigned)idx);
        }

    __syncthreads();
    if (tid < 128)
        g_idx1[b * MM + i0 + tid] = (int)(srow[tid] & 0xFFFFFFFFULL);
    for (int v = tid; v < 1024; v += 512)
        atomicMin(&g_idx2p[b * MM + v], scol[v]);
}

// ---------------- K3: staged gather (uint4) + vicreg stats + fused final --------
__global__ void __launch_bounds__(128) k_stats(float* __restrict__ out) {
    __shared__ __align__(16) uint32_t Raw[2][16][68];       // stride 272B (16B aligned)
    __shared__ __align__(16) __nv_bfloat16 Xb[2][16][136];
    __shared__ float sred[12];
    __shared__ int sidx[16];
    __shared__ int amLast;
    int i = blockIdx.x;
    int p = blockIdx.y;
    int c = threadIdx.x;
    const __nv_bfloat16* tx_ = p ? g_h2 : g_h1;
    const __nv_bfloat16* ty_ = p ? g_h1 : g_h2;

    if (c < 16)
        sidx[c] = p ? (int)(g_idx2p[c * MM + i] & 0xFFFFFFFFULL) : g_idx1[c * MM + i];
    __syncthreads();

    // stage: 512 uint4 chunks (2 halves x 16 b x 16 w4), 4 per thread
#pragma unroll
    for (int q = 0; q < 4; q++) {
        int id = c + q * 128;
        int w4 = id & 15;
        int b = (id >> 4) & 15;
        int half = id >> 8;
        const __nv_bfloat16* src = half ? (ty_ + ((size_t)b * MM + sidx[b]) * 128)
                                        : (tx_ + ((size_t)b * MM + i) * 128);
        uint4 v = ((const uint4*)src)[w4];
        *(uint4*)&Raw[half][b][w4 * 4] = v;
    }
    __syncthreads();

    float x[16], y[16];
#pragma unroll
    for (int b = 0; b < 16; b++) {
        x[b] = __bfloat162float(((const __nv_bfloat16*)&Raw[0][b][0])[c]);
        y[b] = __bfloat162float(((const __nv_bfloat16*)&Raw[1][b][0])[c]);
    }

    float repr = 0.f;
#pragma unroll
    for (int b = 0; b < 16; b++) { float d = x[b] - y[b]; repr += d * d; }

    float mux = 0.f, muy = 0.f;
#pragma unroll
    for (int b = 0; b < 16; b++) { mux += x[b]; muy += y[b]; }
    mux *= (1.f / 16.f); muy *= (1.f / 16.f);

    float sx = 0.f, sy = 0.f;
#pragma unroll
    for (int b = 0; b < 16; b++) {
        x[b] -= mux; sx += x[b] * x[b];
        y[b] -= muy; sy += y[b] * y[b];
    }
    float stdp = fmaxf(0.f, 1.f - sqrtf(sx * (1.f / 15.f) + 1e-4f))
               + fmaxf(0.f, 1.f - sqrtf(sy * (1.f / 15.f) + 1e-4f));
    float S2 = sx * sx + sy * sy;

#pragma unroll
    for (int b = 0; b < 16; b++) {
        Xb[0][b][c] = __float2bfloat16(x[b]);
        Xb[1][b][c] = __float2bfloat16(y[b]);
    }
    __syncthreads();

    float covpart = -S2;
    int wid = c >> 5, l = c & 31;
    if (wid < 2) {
        int t = wid;
        int rowA = (l & 7) + ((l >> 3) & 1) * 8;
        int koffA = (l >> 4) * 8;
        int rowB = (l & 7) + ((l >> 4) & 1) * 8;
        int koffB = ((l >> 3) & 1) * 8;
        uint32_t tb = smem_u32(&Xb[0][0][0]) + (uint32_t)t * 16 * 272;
        uint32_t aB = tb + (uint32_t)rowA * 272 + koffA * 2;
        uint32_t bB = tb + (uint32_t)rowB * 272 + koffB * 2;
        float acc[8];
#pragma unroll
        for (int r = 0; r < 8; r++) acc[r] = 0.f;
#pragma unroll
        for (int ks = 0; ks < 8; ks++) {
            uint32_t a0, a1, a2, a3, b0, b1, b2, b3;
            LDMX4(a0, a1, a2, a3, aB + ks * 32);
            LDMX4(b0, b1, b2, b3, bB + ks * 32);
            MMA16816(acc,     a0, a1, a2, a3, b0, b1);
            MMA16816(acc + 4, a0, a1, a2, a3, b2, b3);
        }
#pragma unroll
        for (int r = 0; r < 8; r++)
            covpart = fmaf(acc[r], acc[r], covpart);
    }

    float v0 = repr, v1 = stdp, v2 = covpart;
#pragma unroll
    for (int off = 16; off >= 1; off >>= 1) {
        v0 += __shfl_down_sync(0xFFFFFFFFu, v0, off);
        v1 += __shfl_down_sync(0xFFFFFFFFu, v1, off);
        v2 += __shfl_down_sync(0xFFFFFFFFu, v2, off);
    }
    if ((c & 31) == 0) { sred[wid] = v0; sred[4 + wid] = v1; sred[8 + wid] = v2; }
    __syncthreads();
    if (c == 0) {
        int blk = p * 1024 + i;
        g_part[0][blk] = sred[0] + sred[1] + sred[2] + sred[3];
        g_part[1][blk] = sred[4] + sred[5] + sred[6] + sred[7];
        g_part[2][blk] = sred[8] + sred[9] + sred[10] + sred[11];
        __threadfence();
        amLast = (atomicAdd(&g_done, 1) == 2047);
    }
    __syncthreads();

    if (amLast) {
        __shared__ float fred[3][4];
#pragma unroll 1
        for (int s = 0; s < 3; s++) {
            float v = 0.f;
            for (int k = c; k < 2048; k += 128) v += g_part[s][k];
#pragma unroll
            for (int off = 16; off >= 1; off >>= 1)
                v += __shfl_down_sync(0xFFFFFFFFu, v, off);
            if ((c & 31) == 0) fred[s][c >> 5] = v;
        }
        __syncthreads();
        if (c < 3) {
            float tot = fred[c][0] + fred[c][1] + fred[c][2] + fred[c][3];
            float scale;
            if (c == 0)      scale = 25.f / (2.f * 2097152.f);
            else if (c == 1) scale = 25.f / (4.f * 131072.f);
            else             scale = 1.f / (225.f * 524288.f);
            out[c] = tot * scale;
        }
    }
}

// ---------------- launch ----------------
extern "C" void kernel_launch(void* const* d_in, const int* in_sizes, int n_in,
                              void* d_out, int out_size) {
    const float* e1 = (const float*)d_in[0];
    const float* e2 = (const float*)d_in[1];
    float* out = (float*)d_out;
    (void)in_sizes; (void)n_in; (void)out_size;

    cudaFuncSetAttribute(k_dots, cudaFuncAttributeMaxDynamicSharedMemorySize, SM_DOTS);

    k_prep<<<dim3(64, 16), 256>>>(e1, e2);
    k_dots<<<dim3(8, 16), 512, SM_DOTS>>>();
    k_stats<<<dim3(MM, 2), 128>>>(out);
}